// round 1
// baseline (speedup 1.0000x reference)
#include <cuda_runtime.h>
#include <cstdint>
#include <cstddef>

#define B_   64
#define T_   512
#define D_   1024
#define H_   1024
#define G3_  3072

// ---------------- scratch (device globals: no allocation allowed) ----------
__device__ float    g_GI[(size_t)T_ * B_ * G3_];   // [T][B][3H] input-side gates
__device__ float    g_h[2][B_ * H_];               // ping-pong hidden state
__device__ unsigned g_count;                       // barrier arrival counter
__device__ unsigned g_release;                     // barrier generation

// ---------------- helpers --------------------------------------------------
__device__ __forceinline__ float f2tf(float x) {   // round-to-nearest tf32
  unsigned u;
  asm("cvt.rna.tf32.f32 %0, %1;" : "=r"(u) : "f"(x));
  return __uint_as_float(u);
}

__device__ __forceinline__ void mma_tf32(float c[4], const unsigned a[4],
                                         const unsigned b[2]) {
  asm volatile(
      "mma.sync.aligned.m16n8k8.row.col.f32.tf32.tf32.f32 "
      "{%0,%1,%2,%3},{%4,%5,%6,%7},{%8,%9},{%0,%1,%2,%3};\n"
      : "+f"(c[0]), "+f"(c[1]), "+f"(c[2]), "+f"(c[3])
      : "r"(a[0]), "r"(a[1]), "r"(a[2]), "r"(a[3]), "r"(b[0]), "r"(b[1]));
}

__device__ __forceinline__ float ldcg(const float* p) { return __ldcg(p); }
__device__ __forceinline__ float4 ldcg4(const float* p) {
  return __ldcg((const float4*)p);
}

// sense-reversing grid barrier; all CTAs resident (grid <= #SMs)
__device__ __forceinline__ void grid_barrier(unsigned G) {
  __syncthreads();
  if (threadIdx.x == 0) {
    volatile unsigned* rel = &g_release;
    unsigned gen = *rel;                 // read BEFORE arriving (no missed flip)
    __threadfence();                     // publish this CTA's writes
    if (atomicAdd(&g_count, 1u) == G - 1u) {
      g_count = 0u;                      // nobody else touches it right now
      __threadfence();
      atomicAdd(&g_release, 1u);
    } else {
      while (*rel == gen) { }
    }
    __threadfence();                     // acquire
  }
  __syncthreads();
}

// ============================================================================
// Phase 1: GI[t][b][c] = sum_k X[b][t][k] * W_ih[c][k]  + b_ih[c]
// TF32 mma.sync GEMM, CTA tile 128(M) x 64(N), K-chunk 32, 8 warps (4x2),
// warp tile 32x32 (2 m16-tiles x 4 n8-tiles).
// ============================================================================
__global__ void __launch_bounds__(256) gi_gemm_kernel(
    const float* __restrict__ X, const float* __restrict__ Wih,
    const float* __restrict__ bih) {
  __shared__ float As[128][36];   // stride 36 -> conflict-free (4g+tg) frags
  __shared__ float Bs[64][36];

  const int tid  = threadIdx.x;
  const int lane = tid & 31;
  const int warp = tid >> 5;
  const int wm   = warp >> 1;     // 0..3
  const int wn   = warp & 1;      // 0..1
  const int g    = lane >> 2;     // groupID 0..7
  const int tg   = lane & 3;      // thread-in-group
  const int m0   = blockIdx.y * 128;
  const int n0   = blockIdx.x * 64;

  float acc[2][4][4];
#pragma unroll
  for (int i = 0; i < 2; i++)
#pragma unroll
    for (int j = 0; j < 4; j++)
#pragma unroll
      for (int k = 0; k < 4; k++) acc[i][j][k] = 0.f;

  const int arow = tid >> 3;          // 0..31
  const int acol = (tid & 7) * 4;     // 0..28

  for (int k0 = 0; k0 < D_; k0 += 32) {
#pragma unroll
    for (int i = 0; i < 4; i++) {
      int row = arow + i * 32;
      float4 v = *(const float4*)(X + (size_t)(m0 + row) * D_ + k0 + acol);
      As[row][acol + 0] = f2tf(v.x);
      As[row][acol + 1] = f2tf(v.y);
      As[row][acol + 2] = f2tf(v.z);
      As[row][acol + 3] = f2tf(v.w);
    }
#pragma unroll
    for (int i = 0; i < 2; i++) {
      int row = arow + i * 32;
      float4 v = *(const float4*)(Wih + (size_t)(n0 + row) * D_ + k0 + acol);
      Bs[row][acol + 0] = f2tf(v.x);
      Bs[row][acol + 1] = f2tf(v.y);
      Bs[row][acol + 2] = f2tf(v.z);
      Bs[row][acol + 3] = f2tf(v.w);
    }
    __syncthreads();

#pragma unroll
    for (int ks = 0; ks < 4; ks++) {
      const int kk = ks * 8;
      unsigned a[2][4], b[4][2];
#pragma unroll
      for (int mt = 0; mt < 2; mt++) {
        int rb = wm * 32 + mt * 16;
        a[mt][0] = __float_as_uint(As[rb + g][kk + tg]);
        a[mt][1] = __float_as_uint(As[rb + g + 8][kk + tg]);
        a[mt][2] = __float_as_uint(As[rb + g][kk + tg + 4]);
        a[mt][3] = __float_as_uint(As[rb + g + 8][kk + tg + 4]);
      }
#pragma unroll
      for (int nt = 0; nt < 4; nt++) {
        int cb = wn * 32 + nt * 8 + g;
        b[nt][0] = __float_as_uint(Bs[cb][kk + tg]);
        b[nt][1] = __float_as_uint(Bs[cb][kk + tg + 4]);
      }
#pragma unroll
      for (int mt = 0; mt < 2; mt++)
#pragma unroll
        for (int nt = 0; nt < 4; nt++) mma_tf32(acc[mt][nt], a[mt], b[nt]);
    }
    __syncthreads();
  }

  // epilogue: add bias, scatter rows (b,t) -> GI[t][b][*]
#pragma unroll
  for (int mt = 0; mt < 2; mt++) {
#pragma unroll
    for (int half = 0; half < 2; half++) {
      int r_loc = wm * 32 + mt * 16 + g + half * 8;
      int r = m0 + r_loc;
      int bb = r >> 9;        // batch
      int tt = r & (T_ - 1);  // time
#pragma unroll
      for (int nt = 0; nt < 4; nt++) {
        int c = n0 + wn * 32 + nt * 8 + 2 * tg;
        float2 bias = *(const float2*)(bih + c);
        float2 o;
        o.x = acc[mt][nt][half * 2 + 0] + bias.x;
        o.y = acc[mt][nt][half * 2 + 1] + bias.y;
        *(float2*)(g_GI + ((size_t)tt * B_ + bb) * G3_ + c) = o;
      }
    }
  }
}

// ============================================================================
// Phase 2: persistent recurrent kernel. 128 CTAs, 128 threads (4 warps).
// Each CTA owns NC=8 hidden columns -> 24 W_hh gate rows, kept in SMEM
// (tf32-rounded) for all 512 steps. Per step:
//   gh[64 x 24] = h[64 x 1024] @ Wslice^T  via tf32 mma (warp = 16 batch rows)
//   fused gate math, write Y[:,t,:] and ping-pong h.
// ============================================================================
#define NC        8
#define NG        24
#define GRID2     128
#define KB2       64
#define WS_STRIDE 1028
#define HS_STRIDE 68
#define SMEM2_FLOATS (NG * WS_STRIDE + 64 * HS_STRIDE)
#define SMEM2_BYTES  (SMEM2_FLOATS * 4)

__global__ void __launch_bounds__(128) gru_step_kernel(
    const float* __restrict__ Whh, const float* __restrict__ bhh,
    const float* __restrict__ h0, float* __restrict__ out) {
  extern __shared__ float smem[];
  float* Ws = smem;                       // [NG][WS_STRIDE]
  float* hs = smem + NG * WS_STRIDE;      // [64][HS_STRIDE]

  const int tid  = threadIdx.x;
  const int lane = tid & 31;
  const int w    = tid >> 5;              // warp 0..3 -> batch rows w*16..
  const int g    = lane >> 2;
  const int tg   = lane & 3;
  const int j0   = blockIdx.x * NC;

  // Load this CTA's W_hh slice into SMEM (tf32-rounded), once.
  // Ws row rw (0..23): gate = rw>>3, col = rw&7 -> global row gate*H + j0 + col
  for (int idx = tid; idx < NG * (D_ / 4); idx += 128) {
    int rw  = idx / (D_ / 4);
    int k4  = (idx % (D_ / 4)) * 4;
    int row = ((rw >> 3) * H_) + j0 + (rw & 7);
    float4 v = *(const float4*)(Whh + (size_t)row * H_ + k4);
    float* dst = Ws + (size_t)rw * WS_STRIDE + k4;
    dst[0] = f2tf(v.x); dst[1] = f2tf(v.y);
    dst[2] = f2tf(v.z); dst[3] = f2tf(v.w);
  }

  // b_hh baked into accumulator init (added to gh BEFORE r*gh_n multiply)
  float bh[3][2];
#pragma unroll
  for (int gate = 0; gate < 3; gate++) {
    bh[gate][0] = bhh[gate * H_ + j0 + 2 * tg];
    bh[gate][1] = bhh[gate * H_ + j0 + 2 * tg + 1];
  }
  __syncthreads();

  const unsigned G = gridDim.x;

  for (int t = 0; t < T_; t++) {
    const float* hc = (t == 0) ? h0 : g_h[t & 1];
    float* hn = g_h[(t + 1) & 1];

    float acc[3][4];
#pragma unroll
    for (int nt = 0; nt < 3; nt++) {
      acc[nt][0] = bh[nt][0]; acc[nt][1] = bh[nt][1];
      acc[nt][2] = bh[nt][0]; acc[nt][3] = bh[nt][1];
    }

    const int hrow = tid >> 4;            // 0..7
    const int hcol = (tid & 15) * 4;      // 0..60

    for (int kc = 0; kc < D_; kc += KB2) {
      // stage h chunk [64 x 64] via L2 (.cg: other SMs wrote it)
#pragma unroll
      for (int i = 0; i < 8; i++) {
        int row = hrow + i * 8;
        float4 v = ldcg4(hc + (size_t)row * H_ + kc + hcol);
        float* dst = hs + (size_t)row * HS_STRIDE + hcol;
        dst[0] = f2tf(v.x); dst[1] = f2tf(v.y);
        dst[2] = f2tf(v.z); dst[3] = f2tf(v.w);
      }
      __syncthreads();
#pragma unroll
      for (int ks = 0; ks < KB2 / 8; ks++) {
        int kk = ks * 8;
        unsigned a[4];
        a[0] = __float_as_uint(hs[(size_t)(w * 16 + g) * HS_STRIDE + kk + tg]);
        a[1] = __float_as_uint(hs[(size_t)(w * 16 + g + 8) * HS_STRIDE + kk + tg]);
        a[2] = __float_as_uint(hs[(size_t)(w * 16 + g) * HS_STRIDE + kk + tg + 4]);
        a[3] = __float_as_uint(hs[(size_t)(w * 16 + g + 8) * HS_STRIDE + kk + tg + 4]);
#pragma unroll
        for (int nt = 0; nt < 3; nt++) {
          unsigned b[2];
          b[0] = __float_as_uint(Ws[(size_t)(nt * 8 + g) * WS_STRIDE + kc + kk + tg]);
          b[1] = __float_as_uint(Ws[(size_t)(nt * 8 + g) * WS_STRIDE + kc + kk + tg + 4]);
          mma_tf32(acc[nt], a, b);
        }
      }
      __syncthreads();
    }

    // fused gate math (r,z,n live in acc[0..2] of the SAME thread)
#pragma unroll
    for (int i = 0; i < 4; i++) {
      int bb = w * 16 + g + ((i >> 1) ? 8 : 0);
      int jj = 2 * tg + (i & 1);
      int j  = j0 + jj;
      size_t gio = ((size_t)t * B_ + bb) * G3_ + j;
      float gir = g_GI[gio];
      float giz = g_GI[gio + H_];
      float gin = g_GI[gio + 2 * H_];
      float hv  = ldcg(hc + (size_t)bb * H_ + j);
      float r = 1.f / (1.f + __expf(-(gir + acc[0][i])));
      float z = 1.f / (1.f + __expf(-(giz + acc[1][i])));
      float nn = tanhf(gin + r * acc[2][i]);
      float hnew = (1.f - z) * nn + z * hv;
      hn[(size_t)bb * H_ + j] = hnew;
      out[((size_t)bb * T_ + t) * H_ + j] = hnew;
      if (t == T_ - 1)
        out[(size_t)B_ * T_ * H_ + (size_t)bb * H_ + j] = hnew;
    }

    if (t < T_ - 1) grid_barrier(G);
  }
}

// ============================================================================
extern "C" void kernel_launch(void* const* d_in, const int* in_sizes, int n_in,
                              void* d_out, int out_size) {
  const float* X   = (const float*)d_in[0];   // Xt  [B,T,D]
  const float* Wih = (const float*)d_in[1];   // [3H,D]
  const float* Whh = (const float*)d_in[2];   // [3H,H]
  const float* bih = (const float*)d_in[3];   // [3H]
  const float* bhh = (const float*)d_in[4];   // [3H]
  const float* h0  = (const float*)d_in[5];   // [B,H]
  float* out = (float*)d_out;                 // Yt [B,T,H] then h_last [B,H]

  cudaFuncSetAttribute(gru_step_kernel,
                       cudaFuncAttributeMaxDynamicSharedMemorySize,
                       SMEM2_BYTES);

  // Phase 1: input-side GEMM for all timesteps
  gi_gemm_kernel<<<dim3(G3_ / 64, (B_ * T_) / 128), 256>>>(X, Wih, bih);

  // Phase 2: persistent recurrence (128 co-resident CTAs, grid barrier)
  gru_step_kernel<<<GRID2, 128, SMEM2_BYTES>>>(Whh, bhh, h0, out);
}

// round 3
// speedup vs baseline: 2.0708x; 2.0708x over previous
#include <cuda_runtime.h>
#include <cstdint>
#include <cstddef>

#define B_   64
#define T_   512
#define D_   1024
#define H_   1024
#define G3_  3072
#define MTOT (B_ * T_)   // 32768

// ---------------- scratch (device globals: no allocation allowed) ----------
__device__ float    g_GI[(size_t)T_ * B_ * G3_];   // [T][B][3H]
__device__ float    g_h[2][B_ * H_];               // ping-pong hidden state
__device__ unsigned g_count;
__device__ unsigned g_release;

// ---------------- helpers --------------------------------------------------
__device__ __forceinline__ float f2tf(float x) {   // round-to-nearest tf32
  unsigned u;
  asm("cvt.rna.tf32.f32 %0, %1;" : "=r"(u) : "f"(x));
  return __uint_as_float(u);
}

__device__ __forceinline__ void mma_tf32(float c[4], const unsigned a[4],
                                         const unsigned b[2]) {
  asm volatile(
      "mma.sync.aligned.m16n8k8.row.col.f32.tf32.tf32.f32 "
      "{%0,%1,%2,%3},{%4,%5,%6,%7},{%8,%9},{%0,%1,%2,%3};\n"
      : "+f"(c[0]), "+f"(c[1]), "+f"(c[2]), "+f"(c[3])
      : "r"(a[0]), "r"(a[1]), "r"(a[2]), "r"(a[3]), "r"(b[0]), "r"(b[1]));
}

__device__ __forceinline__ float  ldcg(const float* p) { return __ldcg(p); }
__device__ __forceinline__ float4 ldcg4(const float* p) {
  return __ldcg((const float4*)p);
}

// sense-reversing grid barrier (all CTAs co-resident)
__device__ __forceinline__ void grid_barrier(unsigned G) {
  __syncthreads();
  if (threadIdx.x == 0) {
    volatile unsigned* rel = &g_release;
    unsigned gen = *rel;
    __threadfence();
    if (atomicAdd(&g_count, 1u) == G - 1u) {
      g_count = 0u;
      __threadfence();
      atomicAdd(&g_release, 1u);
    } else {
      while (*rel == gen) { }
    }
    __threadfence();
  }
  __syncthreads();
}

// ============================================================================
// Phase 1: GI = X @ W_ih^T + b_ih.  tf32 mma.sync with k-permutation so every
// fragment load is one LDS.64.  CTA tile 256(M) x 128(N), 8 warps (4x2),
// warp tile 64x64, K-chunk 32, double-buffered SMEM + register prefetch.
//
// k-permutation: mma step s, thread-slot tg consumes global k = kc+8s+2tg,
// slot tg+4 consumes kc+8s+2tg+1 (applied to BOTH A and B; sum order only).
// Fragment loads become contiguous 8B pairs: a0a2 / a1a3 / b0b1.
// ============================================================================
#define P1_STRIDE   40                     // 32 + 8 pad: conflict-free LDS.64
#define P1_ABUF     (256 * P1_STRIDE)      // 10240 floats
#define P1_BUF      (P1_ABUF + 128 * P1_STRIDE)  // 15360 floats per stage
#define P1_SMEM_BYTES (2 * P1_BUF * 4)     // 122880 B

__global__ void __launch_bounds__(256) gi_gemm_kernel(
    const float* __restrict__ X, const float* __restrict__ Wih,
    const float* __restrict__ bih) {
  extern __shared__ float sm[];

  const int tid  = threadIdx.x;
  const int lane = tid & 31;
  const int warp = tid >> 5;
  const int wm   = warp >> 1;     // 0..3 -> M offset 64*wm
  const int wn   = warp & 1;      // 0..1 -> N offset 64*wn
  const int g    = lane >> 2;     // 0..7
  const int tg   = lane & 3;      // 0..3
  const int m0   = blockIdx.y * 256;
  const int n0   = blockIdx.x * 128;

  const int r  = tid >> 3;        // 0..31 staging row
  const int kg = tid & 7;         // 0..7  staging k-group (4 floats)

  float acc[4][8][4];
#pragma unroll
  for (int i = 0; i < 4; i++)
#pragma unroll
    for (int j = 0; j < 8; j++)
#pragma unroll
      for (int k = 0; k < 4; k++) acc[i][j][k] = 0.f;

  float4 pA[8], pB[4];

  // ---- prologue: load + store chunk 0 ----
#pragma unroll
  for (int i = 0; i < 8; i++)
    pA[i] = *(const float4*)(X + (size_t)(m0 + r + 32 * i) * D_ + kg * 4);
#pragma unroll
  for (int i = 0; i < 4; i++)
    pB[i] = *(const float4*)(Wih + (size_t)(n0 + r + 32 * i) * D_ + kg * 4);
  {
    float* As = sm;
    float* Bs = sm + P1_ABUF;
#pragma unroll
    for (int i = 0; i < 8; i++) {
      float* d = As + (size_t)(r + 32 * i) * P1_STRIDE + kg * 4;
      d[0] = f2tf(pA[i].x); d[1] = f2tf(pA[i].y);
      d[2] = f2tf(pA[i].z); d[3] = f2tf(pA[i].w);
    }
#pragma unroll
    for (int i = 0; i < 4; i++) {
      float* d = Bs + (size_t)(r + 32 * i) * P1_STRIDE + kg * 4;
      d[0] = f2tf(pB[i].x); d[1] = f2tf(pB[i].y);
      d[2] = f2tf(pB[i].z); d[3] = f2tf(pB[i].w);
    }
  }
  __syncthreads();

  for (int c = 0; c < 32; c++) {
    // prefetch chunk c+1 into registers (overlaps with HMMA below)
    if (c < 31) {
      const int kc = (c + 1) * 32;
#pragma unroll
      for (int i = 0; i < 8; i++)
        pA[i] = *(const float4*)(X + (size_t)(m0 + r + 32 * i) * D_ + kc + kg * 4);
#pragma unroll
      for (int i = 0; i < 4; i++)
        pB[i] = *(const float4*)(Wih + (size_t)(n0 + r + 32 * i) * D_ + kc + kg * 4);
    }

    // compute chunk c from buffer c&1
    {
      const float* As = sm + (size_t)(c & 1) * P1_BUF;
      const float* Bs = As + P1_ABUF;
#pragma unroll
      for (int ks = 0; ks < 4; ks++) {
        unsigned a[4][4];
        unsigned b[8][2];
#pragma unroll
        for (int mt = 0; mt < 4; mt++) {
          int row = wm * 64 + mt * 16 + g;
          float2 lo = *(const float2*)(As + (size_t)row * P1_STRIDE + ks * 8 + 2 * tg);
          float2 hi = *(const float2*)(As + (size_t)(row + 8) * P1_STRIDE + ks * 8 + 2 * tg);
          a[mt][0] = __float_as_uint(lo.x);
          a[mt][1] = __float_as_uint(hi.x);
          a[mt][2] = __float_as_uint(lo.y);
          a[mt][3] = __float_as_uint(hi.y);
        }
#pragma unroll
        for (int nt = 0; nt < 8; nt++) {
          int col = wn * 64 + nt * 8 + g;
          float2 bv = *(const float2*)(Bs + (size_t)col * P1_STRIDE + ks * 8 + 2 * tg);
          b[nt][0] = __float_as_uint(bv.x);
          b[nt][1] = __float_as_uint(bv.y);
        }
#pragma unroll
        for (int mt = 0; mt < 4; mt++)
#pragma unroll
          for (int nt = 0; nt < 8; nt++) mma_tf32(acc[mt][nt], a[mt], b[nt]);
      }
    }

    // stage chunk c+1 into the other buffer
    if (c < 31) {
      float* As = sm + (size_t)((c + 1) & 1) * P1_BUF;
      float* Bs = As + P1_ABUF;
#pragma unroll
      for (int i = 0; i < 8; i++) {
        float* d = As + (size_t)(r + 32 * i) * P1_STRIDE + kg * 4;
        d[0] = f2tf(pA[i].x); d[1] = f2tf(pA[i].y);
        d[2] = f2tf(pA[i].z); d[3] = f2tf(pA[i].w);
      }
#pragma unroll
      for (int i = 0; i < 4; i++) {
        float* d = Bs + (size_t)(r + 32 * i) * P1_STRIDE + kg * 4;
        d[0] = f2tf(pB[i].x); d[1] = f2tf(pB[i].y);
        d[2] = f2tf(pB[i].z); d[3] = f2tf(pB[i].w);
      }
    }
    __syncthreads();
  }

  // ---- epilogue: acc -> GI (+ bias); note N columns are NOT permuted ----
#pragma unroll
  for (int mt = 0; mt < 4; mt++) {
#pragma unroll
    for (int half = 0; half < 2; half++) {
      int mrow = m0 + wm * 64 + mt * 16 + g + half * 8;
      int bb = mrow >> 9;        // batch
      int tt = mrow & (T_ - 1);  // time
      float* go = g_GI + ((size_t)tt * B_ + bb) * G3_;
#pragma unroll
      for (int nt = 0; nt < 8; nt++) {
        int col = n0 + wn * 64 + nt * 8 + 2 * tg;
        float2 bias = *(const float2*)(bih + col);
        float2 o;
        o.x = acc[mt][nt][half * 2 + 0] + bias.x;
        o.y = acc[mt][nt][half * 2 + 1] + bias.y;
        *(float2*)(go + col) = o;
      }
    }
  }
}

// ============================================================================
// Phase 2: persistent recurrent kernel. 128 CTAs x 128 threads. Each CTA owns
// 8 hidden columns (24 W_hh gate rows resident in SMEM, tf32-rounded).
// K-chunk 128 with register prefetch of the next h chunk.
// ============================================================================
#define NC        8
#define NG        24
#define GRID2     128
#define KB2       128
#define WS_STRIDE 1028
#define HS_STRIDE 132
#define SMEM2_FLOATS (NG * WS_STRIDE + 64 * HS_STRIDE)
#define SMEM2_BYTES  (SMEM2_FLOATS * 4)

__global__ void __launch_bounds__(128) gru_step_kernel(
    const float* __restrict__ Whh, const float* __restrict__ bhh,
    const float* __restrict__ h0, float* __restrict__ out) {
  extern __shared__ float smemf[];
  float* Ws = smemf;                       // [NG][WS_STRIDE]
  float* hs = smemf + NG * WS_STRIDE;      // [64][HS_STRIDE]

  const int tid  = threadIdx.x;
  const int lane = tid & 31;
  const int w    = tid >> 5;
  const int g    = lane >> 2;
  const int tg   = lane & 3;
  const int j0   = blockIdx.x * NC;

  for (int idx = tid; idx < NG * (D_ / 4); idx += 128) {
    int rw  = idx / (D_ / 4);
    int k4  = (idx % (D_ / 4)) * 4;
    int row = ((rw >> 3) * H_) + j0 + (rw & 7);
    float4 v = *(const float4*)(Whh + (size_t)row * H_ + k4);
    float* dst = Ws + (size_t)rw * WS_STRIDE + k4;
    dst[0] = f2tf(v.x); dst[1] = f2tf(v.y);
    dst[2] = f2tf(v.z); dst[3] = f2tf(v.w);
  }

  float bh[3][2];
#pragma unroll
  for (int gate = 0; gate < 3; gate++) {
    bh[gate][0] = bhh[gate * H_ + j0 + 2 * tg];
    bh[gate][1] = bhh[gate * H_ + j0 + 2 * tg + 1];
  }
  __syncthreads();

  const unsigned G = gridDim.x;

  for (int t = 0; t < T_; t++) {
    const float* hc = (t == 0) ? h0 : g_h[t & 1];
    float* hn = g_h[(t + 1) & 1];

    float acc[3][4];
#pragma unroll
    for (int nt = 0; nt < 3; nt++) {
      acc[nt][0] = bh[nt][0]; acc[nt][1] = bh[nt][1];
      acc[nt][2] = bh[nt][0]; acc[nt][3] = bh[nt][1];
    }

    float4 pre[16];
#pragma unroll
    for (int i = 0; i < 16; i++) {
      int unit = tid + 128 * i;
      pre[i] = ldcg4(hc + (size_t)(unit >> 5) * H_ + (unit & 31) * 4);
    }

    for (int kc = 0; kc < H_; kc += KB2) {
#pragma unroll
      for (int i = 0; i < 16; i++) {
        int unit = tid + 128 * i;
        float4 v = pre[i];
        float4 tv = make_float4(f2tf(v.x), f2tf(v.y), f2tf(v.z), f2tf(v.w));
        *(float4*)(hs + (size_t)(unit >> 5) * HS_STRIDE + (unit & 31) * 4) = tv;
      }
      __syncthreads();
      if (kc + KB2 < H_) {
#pragma unroll
        for (int i = 0; i < 16; i++) {
          int unit = tid + 128 * i;
          pre[i] = ldcg4(hc + (size_t)(unit >> 5) * H_ + kc + KB2 + (unit & 31) * 4);
        }
      }
#pragma unroll
      for (int ks = 0; ks < KB2 / 8; ks++) {
        int kk = ks * 8;
        unsigned a[4];
        a[0] = __float_as_uint(hs[(size_t)(w * 16 + g) * HS_STRIDE + kk + tg]);
        a[1] = __float_as_uint(hs[(size_t)(w * 16 + g + 8) * HS_STRIDE + kk + tg]);
        a[2] = __float_as_uint(hs[(size_t)(w * 16 + g) * HS_STRIDE + kk + tg + 4]);
        a[3] = __float_as_uint(hs[(size_t)(w * 16 + g + 8) * HS_STRIDE + kk + tg + 4]);
#pragma unroll
        for (int nt = 0; nt < 3; nt++) {
          unsigned b[2];
          b[0] = __float_as_uint(Ws[(size_t)(nt * 8 + g) * WS_STRIDE + kc + kk + tg]);
          b[1] = __float_as_uint(Ws[(size_t)(nt * 8 + g) * WS_STRIDE + kc + kk + tg + 4]);
          mma_tf32(acc[nt], a, b);
        }
      }
      __syncthreads();
    }

#pragma unroll
    for (int i = 0; i < 4; i++) {
      int bb = w * 16 + g + ((i >> 1) ? 8 : 0);
      int jj = 2 * tg + (i & 1);
      int j  = j0 + jj;
      size_t gio = ((size_t)t * B_ + bb) * G3_ + j;
      float gir = g_GI[gio];
      float giz = g_GI[gio + H_];
      float gin = g_GI[gio + 2 * H_];
      float hv  = ldcg(hc + (size_t)bb * H_ + j);
      float rg = 1.f / (1.f + __expf(-(gir + acc[0][i])));
      float zg = 1.f / (1.f + __expf(-(giz + acc[1][i])));
      float nn = tanhf(gin + rg * acc[2][i]);
      float hnew = (1.f - zg) * nn + zg * hv;
      hn[(size_t)bb * H_ + j] = hnew;
      out[((size_t)bb * T_ + t) * H_ + j] = hnew;
      if (t == T_ - 1)
        out[(size_t)B_ * T_ * H_ + (size_t)bb * H_ + j] = hnew;
    }

    if (t < T_ - 1) grid_barrier(G);
  }
}

// ============================================================================
extern "C" void kernel_launch(void* const* d_in, const int* in_sizes, int n_in,
                              void* d_out, int out_size) {
  const float* X   = (const float*)d_in[0];
  const float* Wih = (const float*)d_in[1];
  const float* Whh = (const float*)d_in[2];
  const float* bih = (const float*)d_in[3];
  const float* bhh = (const float*)d_in[4];
  const float* h0  = (const float*)d_in[5];
  float* out = (float*)d_out;

  cudaFuncSetAttribute(gi_gemm_kernel,
                       cudaFuncAttributeMaxDynamicSharedMemorySize,
                       P1_SMEM_BYTES);
  cudaFuncSetAttribute(gru_step_kernel,
                       cudaFuncAttributeMaxDynamicSharedMemorySize,
                       SMEM2_BYTES);

  // Phase 1: input-side GEMM (tf32 mma.sync, k-permuted LDS.64 fragments)
  gi_gemm_kernel<<<dim3(24, 128), 256, P1_SMEM_BYTES>>>(X, Wih, bih);

  // Phase 2: persistent recurrence (128 co-resident CTAs, grid barrier)
  gru_step_kernel<<<GRID2, 128, SMEM2_BYTES>>>(Whh, bhh, h0, out);
}

// round 4
// speedup vs baseline: 2.3361x; 1.1281x over previous
#include <cuda_runtime.h>
#include <cstdint>
#include <cstddef>

#define B_   64
#define T_   512
#define D_   1024
#define H_   1024
#define G3_  3072
#define MTOT (B_ * T_)   // 32768

// ---------------- scratch (device globals: no allocation allowed) ----------
__device__ float    g_GI[(size_t)T_ * B_ * G3_];   // [T][B][3H]
__device__ float    g_Xp[(size_t)MTOT * D_];       // X, tf32-rounded, k-interleaved
__device__ float    g_Wp[(size_t)G3_ * D_];        // W_ih, tf32-rounded, k-interleaved
__device__ float    g_h[2][B_ * H_];               // ping-pong hidden state
__device__ unsigned g_count;
__device__ unsigned g_release;

// ---------------- helpers --------------------------------------------------
__device__ __forceinline__ float f2tf(float x) {   // round-to-nearest tf32
  unsigned u;
  asm("cvt.rna.tf32.f32 %0, %1;" : "=r"(u) : "f"(x));
  return __uint_as_float(u);
}

__device__ __forceinline__ void mma_tf32(float c[4], const unsigned a[4],
                                         const unsigned b[2]) {
  asm volatile(
      "mma.sync.aligned.m16n8k8.row.col.f32.tf32.tf32.f32 "
      "{%0,%1,%2,%3},{%4,%5,%6,%7},{%8,%9},{%0,%1,%2,%3};\n"
      : "+f"(c[0]), "+f"(c[1]), "+f"(c[2]), "+f"(c[3])
      : "r"(a[0]), "r"(a[1]), "r"(a[2]), "r"(a[3]), "r"(b[0]), "r"(b[1]));
}

__device__ __forceinline__ float  ldcg(const float* p) { return __ldcg(p); }
__device__ __forceinline__ float4 ldcg4(const float* p) {
  return __ldcg((const float4*)p);
}

__device__ __forceinline__ uint32_t smem_u32(const void* p) {
  uint32_t a;
  asm("{ .reg .u64 t; cvta.to.shared.u64 t, %1; cvt.u32.u64 %0, t; }"
      : "=r"(a) : "l"(p));
  return a;
}

__device__ __forceinline__ void cp16(uint32_t dst, const void* src) {
  asm volatile("cp.async.cg.shared.global [%0], [%1], 16;"
               :: "r"(dst), "l"(src) : "memory");
}
#define CP_COMMIT() asm volatile("cp.async.commit_group;" ::: "memory")
#define CP_WAIT(n)  asm volatile("cp.async.wait_group %0;" :: "n"(n) : "memory")

// sense-reversing grid barrier (all CTAs co-resident)
__device__ __forceinline__ void grid_barrier(unsigned G) {
  __syncthreads();
  if (threadIdx.x == 0) {
    volatile unsigned* rel = &g_release;
    unsigned gen = *rel;
    __threadfence();
    if (atomicAdd(&g_count, 1u) == G - 1u) {
      g_count = 0u;
      __threadfence();
      atomicAdd(&g_release, 1u);
    } else {
      while (*rel == gen) { }
    }
    __threadfence();
  }
  __syncthreads();
}

// ============================================================================
// Phase 0: prep — tf32-round and k-interleave X, W_ih into g_Xp / g_Wp.
// Within each 8-group: out[2j] = tf32(in[j]); out[2j+1] = tf32(in[j+4]).
// So mma k-slot tg sits at word 2tg, slot tg+4 at word 2tg+1 -> frag = LDS.64.
// ============================================================================
__global__ void __launch_bounds__(256) prep_kernel(const float* __restrict__ X,
                                                   const float* __restrict__ W) {
  const size_t ngX = (size_t)MTOT * D_ / 8;
  const size_t ngW = (size_t)G3_ * D_ / 8;
  size_t stride = (size_t)gridDim.x * blockDim.x;
  for (size_t gi = (size_t)blockIdx.x * blockDim.x + threadIdx.x;
       gi < ngX + ngW; gi += stride) {
    const float* src;
    float* dst;
    size_t off;
    if (gi < ngX) { src = X; dst = g_Xp; off = gi * 8; }
    else          { src = W; dst = g_Wp; off = (gi - ngX) * 8; }
    float4 a = *(const float4*)(src + off);
    float4 b = *(const float4*)(src + off + 4);
    float4 o0 = make_float4(f2tf(a.x), f2tf(b.x), f2tf(a.y), f2tf(b.y));
    float4 o1 = make_float4(f2tf(a.z), f2tf(b.z), f2tf(a.w), f2tf(b.w));
    *(float4*)(dst + off) = o0;
    *(float4*)(dst + off + 4) = o1;
  }
}

// ============================================================================
// Phase 1: GI = X @ W_ih^T + b_ih.  tf32 mma.sync, data pre-converted &
// pre-interleaved in gmem.  CTA 128x128, 4 warps (warp tile 64x64),
// cp.async 2-stage pipeline, K-chunk 32.  2 CTAs/SM.
// ============================================================================
#define P1S        40                    // smem row stride in words (32 + 8 pad)
#define P1_STAGE_W (256 * P1S)           // words per stage (128 A + 128 B rows)
#define P1_SMEM_BYTES (2 * P1_STAGE_W * 4)   // 81920 B

__global__ void __launch_bounds__(128) gi_gemm_kernel(const float* __restrict__ bih) {
  extern __shared__ float sm[];
  const uint32_t sbase = smem_u32(sm);

  const int tid  = threadIdx.x;
  const int lane = tid & 31;
  const int w    = tid >> 5;
  const int wm   = w >> 1;        // 0..1 -> M offset 64*wm
  const int wn   = w & 1;         // 0..1 -> N offset 64*wn
  const int g    = lane >> 2;     // 0..7
  const int tg   = lane & 3;      // 0..3
  const int n0   = blockIdx.x * 128;
  const int m0   = blockIdx.y * 128;

  float acc[4][8][4];
#pragma unroll
  for (int i = 0; i < 4; i++)
#pragma unroll
    for (int j = 0; j < 8; j++)
#pragma unroll
      for (int k = 0; k < 4; k++) acc[i][j][k] = 0.f;

  // ---- async stage of chunk c into buffer c&1 ----
  // thread-op mapping idx = i*128+tid: per quarter-warp banks distinct.
#define P1_ISSUE(c)                                                          \
  do {                                                                       \
    const int kc_ = (c) * 32;                                                \
    const uint32_t db_ = sbase + ((c) & 1) * (P1_STAGE_W * 4);               \
    _Pragma("unroll")                                                        \
    for (int i_ = 0; i_ < 16; i_++) {                                        \
      int idx_ = i_ * 128 + tid;                                             \
      int row_ = idx_ >> 3, q_ = idx_ & 7;                                   \
      const float* src_ = (row_ < 128)                                       \
          ? g_Xp + (size_t)(m0 + row_) * D_ + kc_ + q_ * 4                   \
          : g_Wp + (size_t)(n0 + row_ - 128) * D_ + kc_ + q_ * 4;            \
      cp16(db_ + (uint32_t)(row_ * P1S + q_ * 4) * 4, src_);                 \
    }                                                                        \
    CP_COMMIT();                                                             \
  } while (0)

  P1_ISSUE(0);

  for (int c = 0; c < 32; c++) {
    if (c < 31) { P1_ISSUE(c + 1); CP_WAIT(1); }
    else        { CP_WAIT(0); }
    __syncthreads();

    const float* As = sm + (size_t)(c & 1) * P1_STAGE_W;
    const float* Bs = As + 128 * P1S;
#pragma unroll
    for (int ks = 0; ks < 4; ks++) {
      unsigned a[4][4], b[8][2];
#pragma unroll
      for (int mt = 0; mt < 4; mt++) {
        int row = wm * 64 + mt * 16 + g;
        float2 lo = *(const float2*)(As + (size_t)row * P1S + ks * 8 + 2 * tg);
        float2 hi = *(const float2*)(As + (size_t)(row + 8) * P1S + ks * 8 + 2 * tg);
        a[mt][0] = __float_as_uint(lo.x);
        a[mt][1] = __float_as_uint(hi.x);
        a[mt][2] = __float_as_uint(lo.y);
        a[mt][3] = __float_as_uint(hi.y);
      }
#pragma unroll
      for (int nt = 0; nt < 8; nt++) {
        int col = wn * 64 + nt * 8 + g;
        float2 bv = *(const float2*)(Bs + (size_t)col * P1S + ks * 8 + 2 * tg);
        b[nt][0] = __float_as_uint(bv.x);
        b[nt][1] = __float_as_uint(bv.y);
      }
#pragma unroll
      for (int mt = 0; mt < 4; mt++)
#pragma unroll
        for (int nt = 0; nt < 8; nt++) mma_tf32(acc[mt][nt], a[mt], b[nt]);
    }
    __syncthreads();
  }

  // ---- epilogue: acc -> GI (+ bias) ----
#pragma unroll
  for (int mt = 0; mt < 4; mt++) {
#pragma unroll
    for (int half = 0; half < 2; half++) {
      int mrow = m0 + wm * 64 + mt * 16 + g + half * 8;
      int bb = mrow >> 9;        // batch
      int tt = mrow & (T_ - 1);  // time
      float* go = g_GI + ((size_t)tt * B_ + bb) * G3_;
#pragma unroll
      for (int nt = 0; nt < 8; nt++) {
        int col = n0 + wn * 64 + nt * 8 + 2 * tg;
        float2 bias = *(const float2*)(bih + col);
        float2 o;
        o.x = acc[mt][nt][half * 2 + 0] + bias.x;
        o.y = acc[mt][nt][half * 2 + 1] + bias.y;
        *(float2*)(go + col) = o;
      }
    }
  }
}

// ============================================================================
// Phase 2: persistent recurrent kernel. 128 CTAs x 128 threads; each CTA owns
// 8 hidden columns (24 W_hh gate rows in SMEM, tf32).  K-chunk 128, register
// prefetch of next h chunk, GI/h_prev loads hoisted to step start.
// ============================================================================
#define NC        8
#define NG        24
#define GRID2     128
#define KB2       128
#define WS_STRIDE 1028
#define HS_STRIDE 132
#define SMEM2_FLOATS (NG * WS_STRIDE + 64 * HS_STRIDE)
#define SMEM2_BYTES  (SMEM2_FLOATS * 4)

__global__ void __launch_bounds__(128) gru_step_kernel(
    const float* __restrict__ Whh, const float* __restrict__ bhh,
    const float* __restrict__ h0, float* __restrict__ out) {
  extern __shared__ float smemf[];
  float* Ws = smemf;                       // [NG][WS_STRIDE]
  float* hs = smemf + NG * WS_STRIDE;      // [64][HS_STRIDE]

  const int tid  = threadIdx.x;
  const int lane = tid & 31;
  const int w    = tid >> 5;
  const int g    = lane >> 2;
  const int tg   = lane & 3;
  const int j0   = blockIdx.x * NC;

  for (int idx = tid; idx < NG * (D_ / 4); idx += 128) {
    int rw  = idx / (D_ / 4);
    int k4  = (idx % (D_ / 4)) * 4;
    int row = ((rw >> 3) * H_) + j0 + (rw & 7);
    float4 v = *(const float4*)(Whh + (size_t)row * H_ + k4);
    float* dst = Ws + (size_t)rw * WS_STRIDE + k4;
    dst[0] = f2tf(v.x); dst[1] = f2tf(v.y);
    dst[2] = f2tf(v.z); dst[3] = f2tf(v.w);
  }

  float bh[3][2];
#pragma unroll
  for (int gate = 0; gate < 3; gate++) {
    bh[gate][0] = bhh[gate * H_ + j0 + 2 * tg];
    bh[gate][1] = bhh[gate * H_ + j0 + 2 * tg + 1];
  }
  __syncthreads();

  const unsigned G = gridDim.x;

  for (int t = 0; t < T_; t++) {
    const float* hc = (t == 0) ? h0 : g_h[t & 1];
    float* hn = g_h[(t + 1) & 1];

    float acc[3][4];
#pragma unroll
    for (int nt = 0; nt < 3; nt++) {
      acc[nt][0] = bh[nt][0]; acc[nt][1] = bh[nt][1];
      acc[nt][2] = bh[nt][0]; acc[nt][3] = bh[nt][1];
    }

    // hoisted long-latency loads (GI from DRAM, h_prev from L2/L1)
    float gpre[4][3], hvpre[4];
#pragma unroll
    for (int i = 0; i < 4; i++) {
      int bb = w * 16 + g + ((i >> 1) ? 8 : 0);
      int j  = j0 + 2 * tg + (i & 1);
      size_t gio = ((size_t)t * B_ + bb) * G3_ + j;
      gpre[i][0] = g_GI[gio];
      gpre[i][1] = g_GI[gio + H_];
      gpre[i][2] = g_GI[gio + 2 * H_];
      hvpre[i]   = ldcg(hc + (size_t)bb * H_ + j);
    }

    float4 pre[16];
#pragma unroll
    for (int i = 0; i < 16; i++) {
      int unit = tid + 128 * i;
      pre[i] = ldcg4(hc + (size_t)(unit >> 5) * H_ + (unit & 31) * 4);
    }

    for (int kc = 0; kc < H_; kc += KB2) {
#pragma unroll
      for (int i = 0; i < 16; i++) {
        int unit = tid + 128 * i;
        float4 v = pre[i];
        float4 tv = make_float4(f2tf(v.x), f2tf(v.y), f2tf(v.z), f2tf(v.w));
        *(float4*)(hs + (size_t)(unit >> 5) * HS_STRIDE + (unit & 31) * 4) = tv;
      }
      __syncthreads();
      if (kc + KB2 < H_) {
#pragma unroll
        for (int i = 0; i < 16; i++) {
          int unit = tid + 128 * i;
          pre[i] = ldcg4(hc + (size_t)(unit >> 5) * H_ + kc + KB2 + (unit & 31) * 4);
        }
      }
#pragma unroll
      for (int ks = 0; ks < KB2 / 8; ks++) {
        int kk = ks * 8;
        unsigned a[4];
        a[0] = __float_as_uint(hs[(size_t)(w * 16 + g) * HS_STRIDE + kk + tg]);
        a[1] = __float_as_uint(hs[(size_t)(w * 16 + g + 8) * HS_STRIDE + kk + tg]);
        a[2] = __float_as_uint(hs[(size_t)(w * 16 + g) * HS_STRIDE + kk + tg + 4]);
        a[3] = __float_as_uint(hs[(size_t)(w * 16 + g + 8) * HS_STRIDE + kk + tg + 4]);
#pragma unroll
        for (int nt = 0; nt < 3; nt++) {
          unsigned b[2];
          b[0] = __float_as_uint(Ws[(size_t)(nt * 8 + g) * WS_STRIDE + kc + kk + tg]);
          b[1] = __float_as_uint(Ws[(size_t)(nt * 8 + g) * WS_STRIDE + kc + kk + tg + 4]);
          mma_tf32(acc[nt], a, b);
        }
      }
      __syncthreads();
    }

#pragma unroll
    for (int i = 0; i < 4; i++) {
      int bb = w * 16 + g + ((i >> 1) ? 8 : 0);
      int j  = j0 + 2 * tg + (i & 1);
      float rg = 1.f / (1.f + __expf(-(gpre[i][0] + acc[0][i])));
      float zg = 1.f / (1.f + __expf(-(gpre[i][1] + acc[1][i])));
      float nn = tanhf(gpre[i][2] + rg * acc[2][i]);
      float hnew = (1.f - zg) * nn + zg * hvpre[i];
      hn[(size_t)bb * H_ + j] = hnew;
      out[((size_t)bb * T_ + t) * H_ + j] = hnew;
      if (t == T_ - 1)
        out[(size_t)B_ * T_ * H_ + (size_t)bb * H_ + j] = hnew;
    }

    if (t < T_ - 1) grid_barrier(G);
  }
}

// ============================================================================
extern "C" void kernel_launch(void* const* d_in, const int* in_sizes, int n_in,
                              void* d_out, int out_size) {
  const float* X   = (const float*)d_in[0];
  const float* Wih = (const float*)d_in[1];
  const float* Whh = (const float*)d_in[2];
  const float* bih = (const float*)d_in[3];
  const float* bhh = (const float*)d_in[4];
  const float* h0  = (const float*)d_in[5];
  float* out = (float*)d_out;

  cudaFuncSetAttribute(gi_gemm_kernel,
                       cudaFuncAttributeMaxDynamicSharedMemorySize,
                       P1_SMEM_BYTES);
  cudaFuncSetAttribute(gru_step_kernel,
                       cudaFuncAttributeMaxDynamicSharedMemorySize,
                       SMEM2_BYTES);

  // Phase 0: tf32-round + k-interleave X and W_ih
  prep_kernel<<<2048, 256>>>(X, Wih);

  // Phase 1: input-side GEMM (tf32 mma.sync, cp.async pipeline, 2 CTAs/SM)
  gi_gemm_kernel<<<dim3(24, 256), 128, P1_SMEM_BYTES>>>(bih);

  // Phase 2: persistent recurrence (128 co-resident CTAs, grid barrier)
  gru_step_kernel<<<GRID2, 128, SMEM2_BYTES>>>(Whh, bhh, h0, out);
}

// round 5
// speedup vs baseline: 4.1365x; 1.7707x over previous
#include <cuda_runtime.h>
#include <cuda_fp16.h>
#include <cstdint>
#include <cstddef>

#define B_   64
#define T_   512
#define D_   1024
#define H_   1024
#define G3_  3072
#define MTOT (B_ * T_)   // 32768

// ---------------- scratch (device globals: no allocation allowed) ----------
__device__ float    g_GI[(size_t)T_ * B_ * G3_];   // [T][B][3H]
__device__ __half   g_Xh[(size_t)MTOT * D_];       // X fp16, k-permuted
__device__ __half   g_Wh[(size_t)G3_ * D_];        // W_ih fp16, k-permuted
__device__ __half   g_hp[2][B_ * H_];              // hidden fp16, k-permuted
__device__ unsigned g_count;
__device__ unsigned g_release;

// ---------------- helpers --------------------------------------------------
__device__ __forceinline__ void mma_f16(float c[4], const unsigned a[4],
                                        const unsigned b[2]) {
  asm volatile(
      "mma.sync.aligned.m16n8k16.row.col.f32.f16.f16.f32 "
      "{%0,%1,%2,%3},{%4,%5,%6,%7},{%8,%9},{%0,%1,%2,%3};\n"
      : "+f"(c[0]), "+f"(c[1]), "+f"(c[2]), "+f"(c[3])
      : "r"(a[0]), "r"(a[1]), "r"(a[2]), "r"(a[3]), "r"(b[0]), "r"(b[1]));
}

__device__ __forceinline__ float ldcg(const float* p) { return __ldcg(p); }

__device__ __forceinline__ uint32_t smem_u32(const void* p) {
  uint32_t a;
  asm("{ .reg .u64 t; cvta.to.shared.u64 t, %1; cvt.u32.u64 %0, t; }"
      : "=r"(a) : "l"(p));
  return a;
}

__device__ __forceinline__ void cp16(uint32_t dst, const void* src) {
  asm volatile("cp.async.cg.shared.global [%0], [%1], 16;"
               :: "r"(dst), "l"(src) : "memory");
}
#define CP_COMMIT() asm volatile("cp.async.commit_group;" ::: "memory")
#define CP_WAIT(n)  asm volatile("cp.async.wait_group %0;" :: "n"(n) : "memory")

// sense-reversing grid barrier (all CTAs co-resident)
__device__ __forceinline__ void grid_barrier(unsigned G) {
  __syncthreads();
  if (threadIdx.x == 0) {
    volatile unsigned* rel = &g_release;
    unsigned gen = *rel;
    __threadfence();
    if (atomicAdd(&g_count, 1u) == G - 1u) {
      g_count = 0u;
      __threadfence();
      atomicAdd(&g_release, 1u);
    } else {
      while (*rel == gen) { }
    }
    __threadfence();
  }
  __syncthreads();
}

// k-permutation within each 16-group (so m16n8k16 frags are single LDS.64):
// out pairs: (0,1),(8,9),(2,3),(10,11),(4,5),(12,13),(6,7),(14,15)
__device__ __forceinline__ void perm16_store(__half* dst, const float* in16) {
  __half2 o[8];
  o[0] = __floats2half2_rn(in16[0],  in16[1]);
  o[1] = __floats2half2_rn(in16[8],  in16[9]);
  o[2] = __floats2half2_rn(in16[2],  in16[3]);
  o[3] = __floats2half2_rn(in16[10], in16[11]);
  o[4] = __floats2half2_rn(in16[4],  in16[5]);
  o[5] = __floats2half2_rn(in16[12], in16[13]);
  o[6] = __floats2half2_rn(in16[6],  in16[7]);
  o[7] = __floats2half2_rn(in16[14], in16[15]);
  *(uint4*)dst       = *(const uint4*)&o[0];
  *(uint4*)(dst + 8) = *(const uint4*)&o[4];
}

// forward permuted position of k-index r within its 16-group
__device__ __forceinline__ int permpos(int r) {
  return (r < 8) ? ((r & 1) ? 2 * r - 1 : 2 * r)
                 : ((r & 1) ? 2 * r - 15 : 2 * r - 14);
}

// ============================================================================
// Phase 0: prep — fp16-convert + k-permute X, W_ih, h0.
// ============================================================================
__global__ void __launch_bounds__(256) prep_kernel(const float* __restrict__ X,
                                                   const float* __restrict__ W,
                                                   const float* __restrict__ h0) {
  const size_t nX = (size_t)MTOT * D_ / 16;
  const size_t nW = (size_t)G3_ * D_ / 16;
  const size_t nH = (size_t)B_ * H_ / 16;
  size_t stride = (size_t)gridDim.x * blockDim.x;
  for (size_t gi = (size_t)blockIdx.x * blockDim.x + threadIdx.x;
       gi < nX + nW + nH; gi += stride) {
    const float* src;
    __half* dst;
    if (gi < nX)           { src = X  + gi * 16;        dst = g_Xh + gi * 16; }
    else if (gi < nX + nW) { size_t j = gi - nX;        src = W  + j * 16; dst = g_Wh + j * 16; }
    else                   { size_t j = gi - nX - nW;   src = h0 + j * 16; dst = g_hp[0] + j * 16; }
    float in16[16];
#pragma unroll
    for (int q = 0; q < 4; q++)
      *(float4*)(in16 + 4 * q) = *(const float4*)(src + 4 * q);
    perm16_store(dst, in16);
  }
}

// ============================================================================
// Phase 1: GI = X @ W_ih^T + b_ih.  fp16 m16n8k16 mma.sync.
// CTA 128x128, 4 warps (warp tile 64x64), K-chunk 64, cp.async double buffer.
// 2 CTAs/SM.
// ============================================================================
#define P1S_H      80                    // halfs per smem row (64 data + 16 pad)
#define P1_STAGE_B (256 * 160)           // bytes per stage (256 rows x 160 B)
#define P1_SMEM_BYTES (2 * P1_STAGE_B)   // 81920 B

__global__ void __launch_bounds__(128) gi_gemm_kernel(const float* __restrict__ bih) {
  extern __shared__ __half smh[];
  const uint32_t sbase = smem_u32(smh);

  const int tid  = threadIdx.x;
  const int lane = tid & 31;
  const int w    = tid >> 5;
  const int wm   = w >> 1;
  const int wn   = w & 1;
  const int g    = lane >> 2;
  const int tg   = lane & 3;
  const int n0   = blockIdx.x * 128;
  const int m0   = blockIdx.y * 128;

  float acc[4][8][4];
#pragma unroll
  for (int i = 0; i < 4; i++)
#pragma unroll
    for (int j = 0; j < 8; j++)
#pragma unroll
      for (int k = 0; k < 4; k++) acc[i][j][k] = 0.f;

#define P1_ISSUE(c)                                                           \
  do {                                                                        \
    const int kc_ = (c) * 64;                                                 \
    const uint32_t db_ = sbase + ((c) & 1) * P1_STAGE_B;                      \
    _Pragma("unroll")                                                         \
    for (int i_ = 0; i_ < 16; i_++) {                                         \
      int idx_ = i_ * 128 + tid;                                              \
      int row_ = idx_ >> 3, q_ = idx_ & 7;                                    \
      const __half* src_ = (row_ < 128)                                       \
          ? g_Xh + (size_t)(m0 + row_) * D_ + kc_ + q_ * 8                    \
          : g_Wh + (size_t)(n0 + row_ - 128) * D_ + kc_ + q_ * 8;             \
      cp16(db_ + (uint32_t)(row_ * 160 + q_ * 16), src_);                     \
    }                                                                         \
    CP_COMMIT();                                                              \
  } while (0)

  P1_ISSUE(0);

  for (int c = 0; c < 16; c++) {
    if (c < 15) { P1_ISSUE(c + 1); CP_WAIT(1); }
    else        { CP_WAIT(0); }
    __syncthreads();

    const __half* As = smh + (size_t)(c & 1) * (P1_STAGE_B / 2);
    const __half* Bs = As + 128 * P1S_H;
#pragma unroll
    for (int ks = 0; ks < 4; ks++) {
      unsigned a[4][4], b[8][2];
#pragma unroll
      for (int mt = 0; mt < 4; mt++) {
        int row = wm * 64 + mt * 16 + g;
        uint2 lo = *(const uint2*)(As + (size_t)row * P1S_H + ks * 16 + 4 * tg);
        uint2 hi = *(const uint2*)(As + (size_t)(row + 8) * P1S_H + ks * 16 + 4 * tg);
        a[mt][0] = lo.x; a[mt][1] = hi.x; a[mt][2] = lo.y; a[mt][3] = hi.y;
      }
#pragma unroll
      for (int nt = 0; nt < 8; nt++) {
        int col = wn * 64 + nt * 8 + g;
        uint2 bv = *(const uint2*)(Bs + (size_t)col * P1S_H + ks * 16 + 4 * tg);
        b[nt][0] = bv.x; b[nt][1] = bv.y;
      }
#pragma unroll
      for (int mt = 0; mt < 4; mt++)
#pragma unroll
        for (int nt = 0; nt < 8; nt++) mma_f16(acc[mt][nt], a[mt], b[nt]);
    }
    __syncthreads();
  }

  // ---- epilogue: acc -> GI (+ bias) ----
#pragma unroll
  for (int mt = 0; mt < 4; mt++) {
#pragma unroll
    for (int half = 0; half < 2; half++) {
      int mrow = m0 + wm * 64 + mt * 16 + g + half * 8;
      int bb = mrow >> 9;
      int tt = mrow & (T_ - 1);
      float* go = g_GI + ((size_t)tt * B_ + bb) * G3_;
#pragma unroll
      for (int nt = 0; nt < 8; nt++) {
        int col = n0 + wn * 64 + nt * 8 + 2 * tg;
        float2 bias = *(const float2*)(bih + col);
        float2 o;
        o.x = acc[mt][nt][half * 2 + 0] + bias.x;
        o.y = acc[mt][nt][half * 2 + 1] + bias.y;
        *(float2*)(go + col) = o;
      }
    }
  }
}

// ============================================================================
// Phase 2: persistent recurrence, fp16 m16n8k16. 128 CTAs x 128 threads.
// CTA owns 8 hidden cols (24 W_hh gate rows, fp16 permuted, resident in SMEM).
// Whole h (fp16, permuted, 128 KB) staged per step via cp.async.
// ============================================================================
#define NC     8
#define NG     24
#define GRID2  128
#define WS2    1040   // halfs per Ws row
#define HS2    1040   // halfs per hs row
#define SMEM2_BYTES ((NG * WS2 + 64 * HS2) * 2)   // 183040 B

__global__ void __launch_bounds__(128) gru_step_kernel(
    const float* __restrict__ Whh, const float* __restrict__ bhh,
    const float* __restrict__ h0, float* __restrict__ out) {
  extern __shared__ __half smh2[];
  __half* Ws = smh2;                    // [NG][WS2]
  __half* hs = smh2 + NG * WS2;         // [64][HS2]
  const uint32_t hs_base = smem_u32(hs);

  const int tid  = threadIdx.x;
  const int lane = tid & 31;
  const int w    = tid >> 5;
  const int g    = lane >> 2;
  const int tg   = lane & 3;
  const int j0   = blockIdx.x * NC;

  // load W_hh slice -> fp16 permuted SMEM (once)
  for (int idx = tid; idx < NG * (H_ / 16); idx += 128) {
    int rw  = idx >> 6;           // 0..23
    int grp = idx & 63;           // 16-group within row
    int row = ((rw >> 3) * H_) + j0 + (rw & 7);
    float in16[16];
#pragma unroll
    for (int q = 0; q < 4; q++)
      *(float4*)(in16 + 4 * q) = *(const float4*)(Whh + (size_t)row * H_ + grp * 16 + 4 * q);
    perm16_store(Ws + (size_t)rw * WS2 + grp * 16, in16);
  }

  float bh[3][2];
#pragma unroll
  for (int gate = 0; gate < 3; gate++) {
    bh[gate][0] = bhh[gate * H_ + j0 + 2 * tg];
    bh[gate][1] = bhh[gate * H_ + j0 + 2 * tg + 1];
  }

  // per-thread output coords (4 accum elements)
  int bbv[4], jv[4], jpv[4];
#pragma unroll
  for (int i = 0; i < 4; i++) {
    bbv[i] = w * 16 + g + ((i >> 1) ? 8 : 0);
    jv[i]  = j0 + 2 * tg + (i & 1);
    jpv[i] = (jv[i] & ~15) | permpos(jv[i] & 15);
  }
  __syncthreads();

  const unsigned G = gridDim.x;

  for (int t = 0; t < T_; t++) {
    const __half* hc16 = g_hp[t & 1];

    // hoisted long-latency loads
    float gpre[4][3], hvpre[4];
#pragma unroll
    for (int i = 0; i < 4; i++) {
      size_t gio = ((size_t)t * B_ + bbv[i]) * G3_ + jv[i];
      gpre[i][0] = __ldg(g_GI + gio);
      gpre[i][1] = __ldg(g_GI + gio + H_);
      gpre[i][2] = __ldg(g_GI + gio + 2 * H_);
      hvpre[i] = (t == 0)
          ? __ldg(h0 + (size_t)bbv[i] * H_ + jv[i])
          : ldcg(out + ((size_t)bbv[i] * T_ + (t - 1)) * H_ + jv[i]);
    }

    // stage full h (fp16 permuted) via cp.async
#pragma unroll 8
    for (int i = 0; i < 64; i++) {
      int idx = i * 128 + tid;
      int row = idx >> 7, q = idx & 127;
      cp16(hs_base + (uint32_t)(row * (HS2 * 2) + q * 16),
           hc16 + (size_t)row * H_ + q * 8);
    }
    CP_COMMIT();
    CP_WAIT(0);
    __syncthreads();

    float acc[3][4];
#pragma unroll
    for (int nt = 0; nt < 3; nt++) {
      acc[nt][0] = bh[nt][0]; acc[nt][1] = bh[nt][1];
      acc[nt][2] = bh[nt][0]; acc[nt][3] = bh[nt][1];
    }

    const __half* arow0 = hs + (size_t)(w * 16 + g) * HS2 + 4 * tg;
    const __half* arow1 = arow0 + 8 * HS2;
#pragma unroll 8
    for (int ks = 0; ks < 64; ks++) {
      unsigned a[4];
      uint2 lo = *(const uint2*)(arow0 + ks * 16);
      uint2 hi = *(const uint2*)(arow1 + ks * 16);
      a[0] = lo.x; a[1] = hi.x; a[2] = lo.y; a[3] = hi.y;
#pragma unroll
      for (int nt = 0; nt < 3; nt++) {
        uint2 bv = *(const uint2*)(Ws + (size_t)(nt * 8 + g) * WS2 + ks * 16 + 4 * tg);
        unsigned b[2] = {bv.x, bv.y};
        mma_f16(acc[nt], a, b);
      }
    }

    // gate math + stores
    __half* hn16 = g_hp[(t + 1) & 1];
#pragma unroll
    for (int i = 0; i < 4; i++) {
      float rg = 1.f / (1.f + __expf(-(gpre[i][0] + acc[0][i])));
      float zg = 1.f / (1.f + __expf(-(gpre[i][1] + acc[1][i])));
      float nn = tanhf(gpre[i][2] + rg * acc[2][i]);
      float hnew = (1.f - zg) * nn + zg * hvpre[i];
      out[((size_t)bbv[i] * T_ + t) * H_ + jv[i]] = hnew;
      hn16[(size_t)bbv[i] * H_ + jpv[i]] = __float2half_rn(hnew);
      if (t == T_ - 1)
        out[(size_t)B_ * T_ * H_ + (size_t)bbv[i] * H_ + jv[i]] = hnew;
    }

    if (t < T_ - 1) grid_barrier(G);
  }
}

// ============================================================================
extern "C" void kernel_launch(void* const* d_in, const int* in_sizes, int n_in,
                              void* d_out, int out_size) {
  const float* X   = (const float*)d_in[0];
  const float* Wih = (const float*)d_in[1];
  const float* Whh = (const float*)d_in[2];
  const float* bih = (const float*)d_in[3];
  const float* bhh = (const float*)d_in[4];
  const float* h0  = (const float*)d_in[5];
  float* out = (float*)d_out;

  cudaFuncSetAttribute(gi_gemm_kernel,
                       cudaFuncAttributeMaxDynamicSharedMemorySize,
                       P1_SMEM_BYTES);
  cudaFuncSetAttribute(gru_step_kernel,
                       cudaFuncAttributeMaxDynamicSharedMemorySize,
                       SMEM2_BYTES);

  // Phase 0: fp16-convert + k-permute X, W_ih, h0
  prep_kernel<<<2048, 256>>>(X, Wih, h0);

  // Phase 1: input-side GEMM (fp16 m16n8k16, cp.async pipeline, 2 CTAs/SM)
  gi_gemm_kernel<<<dim3(24, 256), 128, P1_SMEM_BYTES>>>(bih);

  // Phase 2: persistent recurrence (128 co-resident CTAs, grid barrier)
  gru_step_kernel<<<GRID2, 128, SMEM2_BYTES>>>(Whh, bhh, h0, out);
}